// round 16
// baseline (speedup 1.0000x reference)
#include <cuda_runtime.h>

// GraphLoss: B=4, C=3, N=1024, G=2048, L=32
// out (float32): [closs, mloss, matches_gt(12x1025x1025)]
//
// L1 (296 blocks x 512 thr, one wave):
//   [0,192)   nearest: 4 preds/thread, pass-1 tracks packed MIN DISTANCE only
//             (no index bookkeeping in hot loop); winning slice found via u64
//             (dist_bits<<32|slice) min; epilogue rescans the 64 points of
//             the winning slice for the first bit-exact d2==bd -> exact
//             first-occurrence argmin. closs partials + packed sort keys.
//   [192,296) zero-fill of d_out (output is 99.98% zeros).
//   Every CTA triggers PDL after its final global writes.
// L2 (12 blocks x 1024 thr, PDL secondary): griddepcontrol.wait, per-class
//   bitonic sort, chain edges, matches gathers + sparse scatter + mloss;
//   ticketed last block finalizes scalars, resets ticket.

#define BC     12
#define NP     1024
#define GP     2048
#define NP1    1025
#define MAT    (NP1 * NP1)
#define THR    0.05590169943749474f
#define NCHUNK 16
#define CPRED  64
#define NSL    32
#define NB     (BC * NCHUNK)      // 192 nearest blocks
#define ZB     104                // zero blocks
#define GRID1  (NB + ZB)          // 296
#define CB     BC                 // 12 chain blocks

typedef unsigned long long ull;

__device__ unsigned g_keys[BC * NP];
__device__ float    g_closs[BC * NCHUNK];
__device__ float    g_mloss[BC];
__device__ int      d_tick;

// ---- PDL primitives -------------------------------------------------------
__device__ __forceinline__ void pdl_trigger() {
    asm volatile("griddepcontrol.launch_dependents;" ::: "memory");
}
__device__ __forceinline__ void pdl_wait() {
    asm volatile("griddepcontrol.wait;" ::: "memory");
}

// ---- packed f32x2 helpers (Blackwell) -------------------------------------
__device__ __forceinline__ ull f2_add(ull a, ull b) {
    ull r; asm("add.rn.f32x2 %0,%1,%2;" : "=l"(r) : "l"(a), "l"(b)); return r;
}
__device__ __forceinline__ ull f2_mul(ull a, ull b) {
    ull r; asm("mul.rn.f32x2 %0,%1,%2;" : "=l"(r) : "l"(a), "l"(b)); return r;
}
__device__ __forceinline__ ull f2_fma(ull a, ull b, ull c) {
    ull r; asm("fma.rn.f32x2 %0,%1,%2,%3;" : "=l"(r) : "l"(a), "l"(b), "l"(c)); return r;
}
__device__ __forceinline__ ull f2_pack(float lo, float hi) {
    ull r;
    asm("mov.b64 %0,{%1,%2};" : "=l"(r)
        : "r"(__float_as_uint(lo)), "r"(__float_as_uint(hi)));
    return r;
}
__device__ __forceinline__ void f2_unpack(ull p, float& lo, float& hi) {
    unsigned a, b;
    asm("mov.b64 {%0,%1},%2;" : "=r"(a), "=r"(b) : "l"(p));
    lo = __uint_as_float(a); hi = __uint_as_float(b);
}

// ---------------------------------------------------------------------------
// Launch 1: nearest (min-then-rescan) + zero-fill + PDL trigger.
// ---------------------------------------------------------------------------
__global__ void __launch_bounds__(512, 2) nearest_zero_kernel(
    const float* __restrict__ positions,   // [BC,N,3]
    const float* __restrict__ gt_pts,      // [BC,G,2]
    const int*   __restrict__ gt_ins,      // [BC,G]
    const int*   __restrict__ gt_order,    // [BC,G]
    float*       __restrict__ dout,
    int out_size)
{
    const int bx  = blockIdx.x;
    const int tid = threadIdx.x;

    if (bx >= NB) {
        // ---- zero-fill role ----
        const int zb = bx - NB;
        const float4 z4 = make_float4(0.f, 0.f, 0.f, 0.f);
        float4* o4 = (float4*)dout;
        const int n4 = out_size >> 2;
        for (int idx = zb * 512 + tid; idx < n4; idx += ZB * 512)
            o4[idx] = z4;
        if (zb == 0 && tid < (out_size & 3))
            dout[(n4 << 2) + tid] = 0.f;
        pdl_trigger();                         // after this CTA's last writes
        return;
    }

    // ---- nearest role ----
    __shared__ __align__(16) float ngx[GP];    // negated normalized gt x
    __shared__ __align__(16) float ngy[GP];
    __shared__ ull   cand[NSL][CPRED / 4][4];  // (dist_bits<<32)|slice
    __shared__ float swr[2];

    const int c     = bx >> 4;
    const int chunk = bx & 15;

    const float* gp = gt_pts + (size_t)c * GP * 2;
    for (int g = tid; g < GP; g += 512) {
        ngx[g] = -((gp[2 * g + 0] + 30.0f) * (1.0f / 60.0f));
        ngy[g] = -((gp[2 * g + 1] + 15.0f) * (1.0f / 30.0f));
    }
    __syncthreads();

    const int quad  = tid & 15;
    const int slice = tid >> 4;
    const int i0    = chunk * CPRED + quad * 4;

    ull Px[4], Py[4];
    #pragma unroll
    for (int p = 0; p < 4; p++) {
        const float* pp = positions + ((size_t)c * NP + i0 + p) * 3;
        Px[p] = f2_pack(pp[0], pp[0]);
        Py[p] = f2_pack(pp[1], pp[1]);
    }

    const int g0 = slice * 64;
    const ull* gx2 = (const ull*)(ngx + g0);
    const ull* gy2 = (const ull*)(ngy + g0);

    // pass 1: packed min distance only (no index tracking in the hot loop)
    float bd0[4] = {3.4e38f, 3.4e38f, 3.4e38f, 3.4e38f};
    float bd1[4] = {3.4e38f, 3.4e38f, 3.4e38f, 3.4e38f};

    #pragma unroll 8
    for (int it = 0; it < 32; it++) {
        const ull gx = gx2[it];
        const ull gy = gy2[it];
        #pragma unroll
        for (int p = 0; p < 4; p++) {
            const ull dx = f2_add(Px[p], gx);          // px - x[g]
            const ull dy = f2_add(Py[p], gy);
            const ull d2 = f2_fma(dy, dy, f2_mul(dx, dx));
            float d0, d1;
            f2_unpack(d2, d0, d1);                     // register aliasing
            bd0[p] = fminf(bd0[p], d0);                // FMNMX, alu pipe
            bd1[p] = fminf(bd1[p], d1);
        }
    }

    #pragma unroll
    for (int p = 0; p < 4; p++) {
        const float bd = fminf(bd0[p], bd1[p]);        // slice-local min
        cand[slice][quad][p] =
            ((ull)__float_as_uint(bd) << 32) | (unsigned)slice;
    }
    __syncthreads();

    if (tid < CPRED) {
        const int q = tid >> 2, p = tid & 3;
        ull k = cand[0][q][p];
        #pragma unroll
        for (int s = 1; s < NSL; s++) {
            const ull kk = cand[s][q][p];
            if (kk < k) k = kk;       // min dist; tie -> earliest slice
        }
        const float bd  = __uint_as_float((unsigned)(k >> 32));
        const int   win = (int)(k & 0xffffffffu);

        const int gi = chunk * CPRED + tid;
        const float* pp = positions + ((size_t)c * NP + gi) * 3;
        const float px = pp[0], py = pp[1];

        // rescan the winning slice: first bit-exact match == global first-
        // occurrence argmin (same add/mul/fma sequence as the packed lanes)
        int gb = win * 64;
        #pragma unroll 4
        for (int t = 0; t < 64; t++) {
            const int g = win * 64 + t;
            const float dx = px + ngx[g];
            const float dy = py + ngy[g];
            const float d2 = fmaf(dy, dy, dx * dx);
            if (d2 == bd) { gb = g; break; }
        }

        const float nd = sqrtf(fmaxf(bd, 1e-12f));
        const int ins = gt_ins  [(size_t)c * GP + gb];
        const int ord = gt_order[(size_t)c * GP + gb];
        const int ik  = (nd < THR) ? ins : 64;
        g_keys[c * NP + gi] =
            ((unsigned)ik << 15) | (((unsigned)ord & 31u) << 10) | (unsigned)gi;

        float v = fabsf(px + ngx[gb]) + fabsf(py + ngy[gb]);
        #pragma unroll
        for (int o = 16; o > 0; o >>= 1)
            v += __shfl_down_sync(0xffffffffu, v, o);
        if ((tid & 31) == 0) swr[tid >> 5] = v;
    }
    __syncthreads();
    if (tid == 0) g_closs[c * NCHUNK + chunk] = swr[0] + swr[1];
    __syncthreads();                           // all writes done block-wide
    pdl_trigger();                             // release dependent grid
}

// ---------------------------------------------------------------------------
// Launch 2 (PDL secondary): chain + mloss + sparse scatter + ticket finalize.
// ---------------------------------------------------------------------------
__global__ void __launch_bounds__(1024) chain_kernel(
    const float* __restrict__ matches,     // [BC,1025,1025]
    float*       __restrict__ dout)
{
    __shared__ unsigned sk[2][NP];
    __shared__ int   sfwd[NP];
    __shared__ int   sbwd[NP];
    __shared__ float wr[32];
    __shared__ int   slast;

    const int c   = blockIdx.x;
    const int tid = threadIdx.x;

    sfwd[tid] = NP;                        // pre-wait prologue (local only)
    sbwd[tid] = NP;

    pdl_wait();                            // primary's writes now visible

    unsigned key = g_keys[c * NP + tid];

    // bitonic sort: shfl for j<32, double-buffered shared for j>=32
    int buf = 0;
    for (unsigned k = 2; k <= NP; k <<= 1) {
        const bool up = ((tid & k) == 0u);
        for (unsigned j = k >> 1; j > 0; j >>= 1) {
            unsigned other;
            if (j >= 32) {
                sk[buf][tid] = key;
                __syncthreads();
                other = sk[buf][tid ^ j];
                buf ^= 1;
            } else {
                other = __shfl_xor_sync(0xffffffffu, key, j);
            }
            const bool takeMin = (((tid & j) == 0u) == up);
            key = takeMin ? (key < other ? key : other)
                          : (key > other ? key : other);
        }
    }
    __syncthreads();                       // protect final buffer write
    sk[0][tid] = key;
    __syncthreads();

    // adjacent sorted entries with same matched instance -> chain edge
    if (tid < NP - 1) {
        const unsigned a = sk[0][tid], b = sk[0][tid + 1];
        const unsigned ia = a >> 15, ib = b >> 15;
        if (ia == ib && ia < 64u) {
            sfwd[a & 1023u] = (int)(b & 1023u);
            sbwd[b & 1023u] = (int)(a & 1023u);
        }
    }
    __syncthreads();

    const int f = sfwd[tid];
    const int b = sbwd[tid];

    const float* lm = matches + (size_t)c * MAT;
    float v = lm[(size_t)tid * NP1 + f] + lm[(size_t)tid * NP1 + b];

    float* om = dout + 2 + (size_t)c * MAT;
    om[(size_t)tid * NP1 + f] = 1.0f;                  // mNN edge or to_bin
    if (b == NP) om[(size_t)NP * NP1 + tid] = 1.0f;    // from_bin row

    #pragma unroll
    for (int o = 16; o > 0; o >>= 1)
        v += __shfl_down_sync(0xffffffffu, v, o);
    if ((tid & 31) == 0) wr[tid >> 5] = v;
    __syncthreads();
    if (tid < 32) {
        float w = wr[tid];
        #pragma unroll
        for (int o = 16; o > 0; o >>= 1)
            w += __shfl_down_sync(0xffffffffu, w, o);
        if (tid == 0) g_mloss[c] = w;
    }
    __syncthreads();

    // ticket: last block finalizes scalars and resets counter (graph-safe)
    if (tid == 0) {
        __threadfence();
        const int t = atomicAdd(&d_tick, 1);
        slast = (t == CB - 1) ? 1 : 0;
        if (slast) __threadfence();
    }
    __syncthreads();

    if (slast && tid < 32) {
        float cs = 0.0f, ms = 0.0f;
        for (int i2 = tid; i2 < BC * NCHUNK; i2 += 32) cs += g_closs[i2];
        if (tid < BC) ms = g_mloss[tid];
        #pragma unroll
        for (int o = 16; o > 0; o >>= 1) {
            cs += __shfl_down_sync(0xffffffffu, cs, o);
            ms += __shfl_down_sync(0xffffffffu, ms, o);
        }
        if (tid == 0) {
            dout[0] = cs / (float)(BC * NP * 2);
            dout[1] = -ms / (float)(BC * NP);
            d_tick = 0;                        // reset for next replay
        }
    }
}

// ---------------------------------------------------------------------------
extern "C" void kernel_launch(void* const* d_in, const int* in_sizes, int n_in,
                              void* d_out, int out_size)
{
    const float* matches   = (const float*)d_in[0];
    const float* positions = (const float*)d_in[1];
    // d_in[2] = masks (all ones, unused)
    const float* gt_pts    = (const float*)d_in[3];
    const int*   gt_ins    = (const int*)  d_in[4];
    const int*   gt_order  = (const int*)  d_in[5];
    float* out = (float*)d_out;

    nearest_zero_kernel<<<GRID1, 512>>>(positions, gt_pts, gt_ins, gt_order,
                                        out, out_size);

    // PDL secondary: may launch as soon as every L1 CTA has triggered.
    cudaLaunchConfig_t cfg = {};
    cfg.gridDim  = dim3(CB);
    cfg.blockDim = dim3(1024);
    cudaLaunchAttribute attr[1];
    attr[0].id = cudaLaunchAttributeProgrammaticStreamSerialization;
    attr[0].val.programmaticStreamSerializationAllowed = 1;
    cfg.attrs    = attr;
    cfg.numAttrs = 1;
    cudaLaunchKernelEx(&cfg, chain_kernel, matches, out);
}